// round 1
// baseline (speedup 1.0000x reference)
#include <cuda_runtime.h>

#define B_   512
#define M_   256
#define BM_  (B_*M_)      // 131072 rows
#define NGL  4
#define NRB  3

// Scratch (allocation-free rule: __device__ globals)
__device__ float g_Y[BM_*128];
__device__ float g_X[BM_*128];
__device__ float g_H[BM_*128];

// ---------------------------------------------------------------------------
// Y[r,n] = op( sum_k X[r,k]*W[n,k] (+bias[n]) ) (+ res[r,n])
// R multiple of 128, K=128, N=128. 128x128 tile per block, 256 threads,
// 8x8 accumulators per thread.
// ---------------------------------------------------------------------------
template<bool HAS_BIAS, bool RELU, bool RES>
__global__ __launch_bounds__(256)
void gemm128(const float* __restrict__ X, const float* __restrict__ W,
             const float* __restrict__ bias, const float* __restrict__ res,
             float* __restrict__ Y)
{
    __shared__ float Xs[128][33];
    __shared__ float Ws[128][33];
    const int tid = threadIdx.x;
    const int tx = tid & 15, ty = tid >> 4;
    const long row0 = (long)blockIdx.x * 128;

    float acc[8][8];
#pragma unroll
    for (int i = 0; i < 8; i++)
#pragma unroll
        for (int j = 0; j < 8; j++) acc[i][j] = 0.f;

    for (int kc = 0; kc < 128; kc += 32) {
#pragma unroll
        for (int it = 0; it < 16; it++) {
            int idx = tid + it * 256;
            int r = idx >> 5, k = idx & 31;
            Xs[r][k] = X[(row0 + r) * 128 + kc + k];
            Ws[r][k] = W[r * 128 + kc + k];
        }
        __syncthreads();
#pragma unroll 8
        for (int k = 0; k < 32; k++) {
            float a[8], w[8];
#pragma unroll
            for (int i = 0; i < 8; i++) a[i] = Xs[ty + 16 * i][k];
#pragma unroll
            for (int j = 0; j < 8; j++) w[j] = Ws[tx + 16 * j][k];
#pragma unroll
            for (int i = 0; i < 8; i++)
#pragma unroll
                for (int j = 0; j < 8; j++)
                    acc[i][j] = fmaf(a[i], w[j], acc[i][j]);
        }
        __syncthreads();
    }

#pragma unroll
    for (int j = 0; j < 8; j++) {
        int col = tx + 16 * j;
        float bv = HAS_BIAS ? bias[col] : 0.f;
#pragma unroll
        for (int i = 0; i < 8; i++) {
            long row = row0 + ty + 16 * i;
            float v = acc[i][j] + bv;
            if (RELU) v = fmaxf(v, 0.f);
            if (RES)  v += res[row * 128 + col];
            Y[row * 128 + col] = v;
        }
    }
}

// ---------------------------------------------------------------------------
// Xout[b,m,p] = relu( sum_n G0[b,m,n] * Yin[b,n,p] ),  M=256, N(p)=128, K(n)=256
// grid (2, 512): 128-row tile x full 128 cols per block.
// ---------------------------------------------------------------------------
__global__ __launch_bounds__(256)
void bmm_relu(const float* __restrict__ G, const float* __restrict__ Yin,
              float* __restrict__ Xout)
{
    __shared__ float As[128][33];
    __shared__ float Bs[32][129];
    const int tid = threadIdx.x;
    const int tx = tid & 15, ty = tid >> 4;
    const int b = blockIdx.y;
    const int row0 = blockIdx.x * 128;
    const float* A  = G   + (long)b * M_ * M_;
    const float* Bm = Yin + (long)b * M_ * 128;

    float acc[8][8];
#pragma unroll
    for (int i = 0; i < 8; i++)
#pragma unroll
        for (int j = 0; j < 8; j++) acc[i][j] = 0.f;

    for (int kc = 0; kc < 256; kc += 32) {
#pragma unroll
        for (int it = 0; it < 16; it++) {
            int idx = tid + it * 256;
            int r = idx >> 5, k = idx & 31;
            As[r][k] = A[(row0 + r) * 256 + kc + k];
        }
#pragma unroll
        for (int it = 0; it < 16; it++) {
            int idx = tid + it * 256;
            int k = idx >> 7, n = idx & 127;
            Bs[k][n] = Bm[(kc + k) * 128 + n];
        }
        __syncthreads();
#pragma unroll 8
        for (int k = 0; k < 32; k++) {
            float a[8], w[8];
#pragma unroll
            for (int i = 0; i < 8; i++) a[i] = As[ty + 16 * i][k];
#pragma unroll
            for (int j = 0; j < 8; j++) w[j] = Bs[k][tx + 16 * j];
#pragma unroll
            for (int i = 0; i < 8; i++)
#pragma unroll
                for (int j = 0; j < 8; j++)
                    acc[i][j] = fmaf(a[i], w[j], acc[i][j]);
        }
        __syncthreads();
    }

    float* O = Xout + (long)b * M_ * 128;
#pragma unroll
    for (int j = 0; j < 8; j++) {
        int col = tx + 16 * j;
#pragma unroll
        for (int i = 0; i < 8; i++) {
            int row = row0 + ty + 16 * i;
            O[row * 128 + col] = fmaxf(acc[i][j], 0.f);
        }
    }
}

// ---------------------------------------------------------------------------
// Fused final: out[r] = f2_b + sum_{n<1024} f2_W[n] * relu( H[r,:]·f1_W[n,:] + f1_b[n] )
// 128-row tile per block; loop n in chunks of 128, k in chunks of 32.
// ---------------------------------------------------------------------------
__global__ __launch_bounds__(256)
void f1f2_fused(const float* __restrict__ H, const float* __restrict__ W1,
                const float* __restrict__ b1, const float* __restrict__ W2,
                const float* __restrict__ b2, float* __restrict__ out)
{
    __shared__ float Xs[128][33];
    __shared__ float Ws[128][33];
    __shared__ float red[128][17];
    const int tid = threadIdx.x;
    const int tx = tid & 15, ty = tid >> 4;
    const long row0 = (long)blockIdx.x * 128;

    float psum[8];
#pragma unroll
    for (int i = 0; i < 8; i++) psum[i] = 0.f;

    for (int nc = 0; nc < 1024; nc += 128) {
        float acc[8][8];
#pragma unroll
        for (int i = 0; i < 8; i++)
#pragma unroll
            for (int j = 0; j < 8; j++) acc[i][j] = 0.f;

        for (int kc = 0; kc < 128; kc += 32) {
#pragma unroll
            for (int it = 0; it < 16; it++) {
                int idx = tid + it * 256;
                int r = idx >> 5, k = idx & 31;
                Xs[r][k] = H[(row0 + r) * 128 + kc + k];
                Ws[r][k] = W1[(long)(nc + r) * 128 + kc + k];
            }
            __syncthreads();
#pragma unroll 8
            for (int k = 0; k < 32; k++) {
                float a[8], w[8];
#pragma unroll
                for (int i = 0; i < 8; i++) a[i] = Xs[ty + 16 * i][k];
#pragma unroll
                for (int j = 0; j < 8; j++) w[j] = Ws[tx + 16 * j][k];
#pragma unroll
                for (int i = 0; i < 8; i++)
#pragma unroll
                    for (int j = 0; j < 8; j++)
                        acc[i][j] = fmaf(a[i], w[j], acc[i][j]);
            }
            __syncthreads();
        }

#pragma unroll
        for (int j = 0; j < 8; j++) {
            int col = nc + tx + 16 * j;
            float bb = b1[col];
            float sc = W2[col];
#pragma unroll
            for (int i = 0; i < 8; i++)
                psum[i] = fmaf(fmaxf(acc[i][j] + bb, 0.f), sc, psum[i]);
        }
    }

#pragma unroll
    for (int i = 0; i < 8; i++) red[ty + 16 * i][tx] = psum[i];
    __syncthreads();
    if (tid < 128) {
        float s = b2[0];
#pragma unroll
        for (int t = 0; t < 16; t++) s += red[tid][t];
        out[row0 + tid] = s;
    }
}

// ---------------------------------------------------------------------------
extern "C" void kernel_launch(void* const* d_in, const int* in_sizes, int n_in,
                              void* d_out, int out_size)
{
    const float* G     = (const float*)d_in[0];
    const float* xG    = (const float*)d_in[1];
    const float* gmlW  = (const float*)d_in[2];
    const float* gmlB  = (const float*)d_in[3];
    const float* lin0W = (const float*)d_in[4];
    const float* lin0B = (const float*)d_in[5];
    const float* rinW  = (const float*)d_in[6];
    const float* rinB  = (const float*)d_in[7];
    const float* rb1W  = (const float*)d_in[8];
    const float* rb1B  = (const float*)d_in[9];
    const float* rb2W  = (const float*)d_in[10];
    const float* routW = (const float*)d_in[11];
    const float* routB = (const float*)d_in[12];
    const float* f1W   = (const float*)d_in[13];
    const float* f1B   = (const float*)d_in[14];
    const float* f2W   = (const float*)d_in[15];
    const float* f2B   = (const float*)d_in[16];
    float* out = (float*)d_out;

    float *bY, *bX, *bH;
    cudaGetSymbolAddress((void**)&bY, g_Y);
    cudaGetSymbolAddress((void**)&bX, g_X);
    cudaGetSymbolAddress((void**)&bH, g_H);

    const int GB = BM_ / 128;   // 1024 blocks
    dim3 blk(256);

    // GNN message-passing layers
    const float* xcur = xG;
    for (int l = 0; l < NGL; l++) {
        gemm128<true, false, false><<<GB, blk>>>(xcur, gmlW + (long)l * 128 * 128,
                                                 gmlB + l * 128, nullptr, bY);
        bmm_relu<<<dim3(2, B_), blk>>>(G, bY, bX);
        xcur = bX;
    }

    // MLP trunk
    gemm128<true, false, false><<<GB, blk>>>(bX, lin0W, lin0B, nullptr, bH);
    gemm128<true, false, false><<<GB, blk>>>(bH, rinW, rinB, nullptr, bX);
    for (int i = 0; i < NRB; i++) {
        gemm128<true, true,  false><<<GB, blk>>>(bX, rb1W + (long)i * 128 * 128,
                                                 rb1B + i * 128, nullptr, bY);
        gemm128<false, false, true><<<GB, blk>>>(bY, rb2W + (long)i * 128 * 128,
                                                 nullptr, bX, bX);
    }
    gemm128<true, false, false><<<GB, blk>>>(bX, routW, routB, nullptr, bH);

    // Fused f1 (relu) + f2 head
    f1f2_fused<<<GB, blk>>>(bH, f1W, f1B, f2W, f2B, out);
}